// round 1
// baseline (speedup 1.0000x reference)
#include <cuda_runtime.h>
#include <math_constants.h>

#define N_  64
#define C_  8
#define L_  2048
#define S_  64
#define K_  128
#define W_  (L_ - S_ + 1)          /* 1985 */
#define WT  128                    /* windows per block tile */
#define NWT ((W_ + WT - 1) / WT)   /* 16 */

// ---------------- device scratch (no allocations allowed) ----------------
__device__ float g_sht[C_][S_][K_];   // z-normed shapelets, transposed [c][s][k]
__device__ float g_sqs[C_][K_];       // sum(sh^2) per (c,k)

// ---------------- f32x2 helpers (sm_103a packed fp32) ----------------
__device__ __forceinline__ unsigned long long pk2(float a, float b) {
    unsigned long long r;
    asm("mov.b64 %0, {%1, %2};" : "=l"(r) : "f"(a), "f"(b));
    return r;
}
__device__ __forceinline__ void upk2(unsigned long long v, float& a, float& b) {
    asm("mov.b64 {%0, %1}, %2;" : "=f"(a), "=f"(b) : "l"(v));
}
__device__ __forceinline__ unsigned long long ffma2(unsigned long long a,
                                                    unsigned long long b,
                                                    unsigned long long c) {
    unsigned long long d;
    asm("fma.rn.f32x2 %0, %1, %2, %3;" : "=l"(d) : "l"(a), "l"(b), "l"(c));
    return d;
}
__device__ __forceinline__ float fast_sqrt(float x) {
    float r;
    asm("sqrt.approx.f32 %0, %1;" : "=f"(r) : "f"(x));
    return r;
}

// ---------------- shapelet z-norm prep ----------------
__global__ void prep_kernel(const float* __restrict__ sh) {
    int c = blockIdx.x;      // 0..7
    int k = threadIdx.x;     // 0..127
    const float* p = sh + ((size_t)c * K_ + k) * S_;

    float sum = 0.f;
#pragma unroll 16
    for (int s = 0; s < S_; s++) sum += p[s];
    float mu = sum * (1.0f / S_);

    float var = 0.f;
#pragma unroll 16
    for (int s = 0; s < S_; s++) { float d = p[s] - mu; var = fmaf(d, d, var); }
    var *= (1.0f / S_);
    float inv = 1.0f / sqrtf(var);

    float sq = 0.f;
#pragma unroll 16
    for (int s = 0; s < S_; s++) {
        float v = (p[s] - mu) * inv;
        g_sht[c][s][k] = v;
        sq = fmaf(v, v, sq);
    }
    g_sqs[c][k] = sq;
}

// ---------------- output init (+inf) ----------------
__global__ void init_kernel(float* out, int n) {
    int i = blockIdx.x * blockDim.x + threadIdx.x;
    if (i < n) out[i] = CUDART_INF_F;
}

// ---------------- main kernel ----------------
// grid: (NWT, N_), block: 256 threads.
// thread tile: 8 w (ty) x 8 k (tx), 16x16 threads cover 128w x 128k.
__global__ __launch_bounds__(256, 1)
void min_dist_kernel(const float* __restrict__ x, float* __restrict__ out) {
    __shared__ float s_sht[S_][K_];        // 32 KB: shapelets for current channel
    __shared__ float s_x[WT + S_];         // 192 floats x strip
    __shared__ float s_sqx[WT];            // window sum-of-squares
    __shared__ float s_sqs[K_];            // shapelet sum-of-squares
    __shared__ int   s_bmin[K_];           // block min (float bits)

    const int n     = blockIdx.y;
    const int wt    = blockIdx.x;
    const int wbase = wt * WT;
    const int tid   = threadIdx.x;
    const int tx    = tid & 15;
    const int ty    = tid >> 4;
    const int w0    = ty * 8;
    const int k0    = tx * 8;

    float acc[8][8];
#pragma unroll
    for (int i = 0; i < 8; i++)
#pragma unroll
        for (int j = 0; j < 8; j++) acc[i][j] = 0.f;

    for (int c = 0; c < C_; c++) {
        __syncthreads();   // protect smem reuse from previous channel

        // stage shapelet tile [64][128] floats = 2048 float4, 8 per thread
        {
            const float4* src = (const float4*)(&g_sht[c][0][0]);
            float4*       dst = (float4*)(&s_sht[0][0]);
#pragma unroll
            for (int i = 0; i < 8; i++) dst[tid + i * 256] = src[tid + i * 256];
        }
        // stage x strip (clamp OOB to 0; those windows are masked from the min)
        if (tid < WT + S_) {
            int gi = wbase + tid;
            s_x[tid] = (gi < L_) ? x[((size_t)n * C_ + c) * L_ + gi] : 0.f;
        }
        if (tid < K_) s_sqs[tid] = g_sqs[c][tid];
        __syncthreads();

        // per-window sum of squares
        if (tid < WT) {
            float a = 0.f;
#pragma unroll 16
            for (int s = 0; s < S_; s++) { float v = s_x[tid + s]; a = fmaf(v, v, a); }
            s_sqx[tid] = a;
        }
        __syncthreads();

        // cross-correlation: 8w x 8k per thread, packed f32x2 over k pairs
        unsigned long long cr[8][4];
#pragma unroll
        for (int i = 0; i < 8; i++)
#pragma unroll
            for (int j = 0; j < 4; j++) cr[i][j] = 0ull;

#pragma unroll 8
        for (int s = 0; s < S_; s++) {
            float4 b0 = *(const float4*)&s_sht[s][k0];
            float4 b1 = *(const float4*)&s_sht[s][k0 + 4];
            unsigned long long B0 = pk2(b0.x, b0.y);
            unsigned long long B1 = pk2(b0.z, b0.w);
            unsigned long long B2 = pk2(b1.x, b1.y);
            unsigned long long B3 = pk2(b1.z, b1.w);
#pragma unroll
            for (int wi = 0; wi < 8; wi++) {
                float av = s_x[w0 + s + wi];
                unsigned long long ad = pk2(av, av);
                cr[wi][0] = ffma2(ad, B0, cr[wi][0]);
                cr[wi][1] = ffma2(ad, B1, cr[wi][1]);
                cr[wi][2] = ffma2(ad, B2, cr[wi][2]);
                cr[wi][3] = ffma2(ad, B3, cr[wi][3]);
            }
        }

        // epilogue: d = sqrt(max(sqx + sqs - 2*cross, 1e-12)), accumulate over c
#pragma unroll
        for (int wi = 0; wi < 8; wi++) {
            float sqx = s_sqx[w0 + wi];
#pragma unroll
            for (int kj = 0; kj < 4; kj++) {
                float c0, c1;
                upk2(cr[wi][kj], c0, c1);
                float t0 = sqx + s_sqs[k0 + 2 * kj];
                float t1 = sqx + s_sqs[k0 + 2 * kj + 1];
                float d0 = fmaf(-2.f, c0, t0);
                float d1 = fmaf(-2.f, c1, t1);
                d0 = fmaxf(d0, 1e-12f);
                d1 = fmaxf(d1, 1e-12f);
                acc[wi][2 * kj]     += fast_sqrt(d0);
                acc[wi][2 * kj + 1] += fast_sqrt(d1);
            }
        }
    }

    // block-level min over w, then global atomic min
    __syncthreads();
    if (tid < K_) s_bmin[tid] = 0x7F800000;  // +inf bits
    __syncthreads();

#pragma unroll
    for (int kj = 0; kj < 8; kj++) {
        float m = CUDART_INF_F;
#pragma unroll
        for (int wi = 0; wi < 8; wi++) {
            if (wbase + w0 + wi < W_) m = fminf(m, acc[wi][kj]);
        }
        atomicMin(&s_bmin[k0 + kj], __float_as_int(m));
    }
    __syncthreads();

    if (tid < K_) {
        // all distances are strictly positive -> int-bit compare == float compare
        atomicMin((int*)&out[(size_t)n * K_ + tid], s_bmin[tid]);
    }
}

// ---------------- launch ----------------
extern "C" void kernel_launch(void* const* d_in, const int* in_sizes, int n_in,
                              void* d_out, int out_size) {
    const float* x  = (const float*)d_in[0];   // (64, 8, 2048)
    const float* sh = (const float*)d_in[1];   // (8, 128, 64)
    float* out = (float*)d_out;                // (64, 1, 128)

    prep_kernel<<<C_, K_>>>(sh);
    init_kernel<<<(out_size + 255) / 256, 256>>>(out, out_size);

    dim3 grid(NWT, N_);
    min_dist_kernel<<<grid, 256>>>(x, out);
}

// round 3
// speedup vs baseline: 2.4514x; 2.4514x over previous
#include <cuda_runtime.h>
#include <cuda_bf16.h>
#include <cstdint>
#include <math_constants.h>

#define N_  64
#define C_  8
#define L_  2048
#define S_  64
#define K_  128
#define W_  (L_ - S_ + 1)          /* 1985 */
#define WT  128
#define NWT ((W_ + WT - 1) / WT)   /* 16 */
#define PAD 72                     /* row pitch in bf16 (144 B) -> conflict-free ldmatrix */

// ---------------- device scratch ----------------
__device__ __align__(16) __nv_bfloat16 g_shb[C_][K_ * PAD]; // z-normed shapelets, padded rows

// ---------------- helpers ----------------
__device__ __forceinline__ uint32_t smem_u32(const void* p) {
    uint32_t a;
    asm("{ .reg .u64 t; cvta.to.shared.u64 t, %1; cvt.u32.u64 %0, t; }" : "=r"(a) : "l"(p));
    return a;
}
__device__ __forceinline__ float fast_sqrt(float x) {
    float r; asm("sqrt.approx.f32 %0, %1;" : "=f"(r) : "f"(x)); return r;
}
__device__ __forceinline__ void ldmatrix_x4(uint32_t& r0, uint32_t& r1, uint32_t& r2, uint32_t& r3,
                                            uint32_t addr) {
    asm volatile("ldmatrix.sync.aligned.m8n8.x4.shared.b16 {%0,%1,%2,%3}, [%4];"
                 : "=r"(r0), "=r"(r1), "=r"(r2), "=r"(r3) : "r"(addr));
}
__device__ __forceinline__ void mma_bf16(float& c0, float& c1, float& c2, float& c3,
                                         uint32_t a0, uint32_t a1, uint32_t a2, uint32_t a3,
                                         uint32_t b0, uint32_t b1) {
    asm volatile("mma.sync.aligned.m16n8k16.row.col.f32.bf16.bf16.f32 "
                 "{%0,%1,%2,%3}, {%4,%5,%6,%7}, {%8,%9}, {%0,%1,%2,%3};"
                 : "+f"(c0), "+f"(c1), "+f"(c2), "+f"(c3)
                 : "r"(a0), "r"(a1), "r"(a2), "r"(a3), "r"(b0), "r"(b1));
}

// ---------------- prep: z-norm shapelets -> padded bf16; also init out ----------------
// grid (C_, 4), block 1024: warp w handles shapelet k = blockIdx.y*32 + w of channel blockIdx.x
__global__ void prep_kernel(const float* __restrict__ sh, float* __restrict__ out) {
    int c = blockIdx.x;
    int wid = threadIdx.x >> 5, lane = threadIdx.x & 31;
    int k = blockIdx.y * 32 + wid;
    const float* p = sh + ((size_t)c * K_ + k) * S_;

    float a = p[lane], b = p[lane + 32];
    float s = a + b;
#pragma unroll
    for (int o = 16; o > 0; o >>= 1) s += __shfl_xor_sync(0xffffffffu, s, o);
    float mu = s * (1.0f / S_);
    float da = a - mu, db = b - mu;
    float v = da * da + db * db;
#pragma unroll
    for (int o = 16; o > 0; o >>= 1) v += __shfl_xor_sync(0xffffffffu, v, o);
    float inv = rsqrtf(v * (1.0f / S_));

    __nv_bfloat16* row = &g_shb[c][(size_t)k * PAD];
    row[lane]      = __float2bfloat16_rn(da * inv);
    row[lane + 32] = __float2bfloat16_rn(db * inv);

    // init out to +inf (8192 elems; use channel-0 blocks: 4*1024 = 4096 threads -> 2 each)
    if (c == 0) {
        int i = blockIdx.y * 1024 + threadIdx.x;
        out[i] = CUDART_INF_F;
        out[i + 4096] = CUDART_INF_F;
    }
}

// ---------------- main kernel ----------------
// grid (NWT, N_), 256 threads (8 warps). Warp w owns rows 16w..16w+15 of the 128x128 tile.
__global__ void __launch_bounds__(256, 1)
min_dist_kernel(const float* __restrict__ x, float* __restrict__ out) {
    __shared__ __align__(16) __nv_bfloat16 smA[K_ * PAD];   // 18432 B Toeplitz windows
    __shared__ __align__(16) __nv_bfloat16 smB[K_ * PAD];   // 18432 B shapelets
    __shared__ float s_strip[WT + S_];                       // 192 f32
    __shared__ float s_sqx[WT];
    __shared__ int   s_min[K_];

    const int tid = threadIdx.x, wid = tid >> 5, lane = tid & 31;
    const int n = blockIdx.y, wbase = blockIdx.x * WT;
    const float* xrow_base = x + (size_t)n * C_ * L_;

    // ldmatrix per-lane base addresses (row = lane&15, col-halves by lane>>4)
    const uint32_t aAddr = smem_u32(smA) + (uint32_t)(wid * 16 + (lane & 15)) * (PAD * 2) + (lane >> 4) * 16;
    const uint32_t bAddrBase = smem_u32(smB) + (uint32_t)(lane & 15) * (PAD * 2) + (lane >> 4) * 16;

    const int g = lane >> 2;           // row-within-quad 0..7
    const int q = lane & 3;            // col group
    const int rl0 = wid * 16 + g;      // local rows this thread owns
    const int rl1 = rl0 + 8;

    float ds[64];
#pragma unroll
    for (int i = 0; i < 64; i++) ds[i] = 0.f;

    for (int c = 0; c < C_; c++) {
        __syncthreads();   // smem reusable (prev channel consumed)

        // stage B (linear 16B copies of pre-padded bf16) + x strip
        {
            const float4* bsrc = (const float4*)&g_shb[c][0];
            float4* bdst = (float4*)smB;
#pragma unroll
            for (int i = 0; i < 5; i++) {
                int idx = tid + i * 256;
                if (idx < (K_ * PAD * 2) / 16) bdst[idx] = bsrc[idx];
            }
            if (tid < WT + S_) {
                int gi = wbase + tid;
                s_strip[tid] = (gi < L_) ? xrow_base[(size_t)c * L_ + gi] : 0.f;
            }
        }
        __syncthreads();

        // build Toeplitz A tile (bf16) + per-window sum of squares
        {
            int row = tid >> 1, s0 = (tid & 1) * 32;
            __nv_bfloat162* arow = (__nv_bfloat162*)&smA[(size_t)row * PAD + s0];
            const float* src = &s_strip[row + s0];
#pragma unroll
            for (int j = 0; j < 16; j++)
                arow[j] = __floats2bfloat162_rn(src[2 * j], src[2 * j + 1]);
        }
        if (tid < WT) {
            float a = 0.f;
#pragma unroll 16
            for (int s = 0; s < S_; s++) { float vv = s_strip[tid + s]; a = fmaf(vv, vv, a); }
            s_sqx[tid] = a;
        }
        __syncthreads();

        // A fragments for this warp's 16 rows, all 4 k-steps
        uint32_t af[4][4];
#pragma unroll
        for (int kk = 0; kk < 4; kk++)
            ldmatrix_x4(af[kk][0], af[kk][1], af[kk][2], af[kk][3], aAddr + kk * 32);

        // sqs(z-normed) == S exactly; fold into per-row constant
        const float t0 = s_sqx[rl0] + (float)S_;
        const float t1 = s_sqx[rl1] + (float)S_;

        // 8 n16-tiles: mma accumulate over k, epilogue immediately (keeps regs low)
#pragma unroll
        for (int t = 0; t < 8; t++) {
            uint32_t bf[4][4];
            uint32_t ba = bAddrBase + (uint32_t)t * (16 * PAD * 2);
#pragma unroll
            for (int kk = 0; kk < 4; kk++)
                ldmatrix_x4(bf[kk][0], bf[kk][1], bf[kk][2], bf[kk][3], ba + kk * 32);

            float cc[8];
#pragma unroll
            for (int e = 0; e < 8; e++) cc[e] = 0.f;
#pragma unroll
            for (int kk = 0; kk < 4; kk++) {
                mma_bf16(cc[0], cc[1], cc[2], cc[3],
                         af[kk][0], af[kk][1], af[kk][2], af[kk][3], bf[kk][0], bf[kk][2]);
                mma_bf16(cc[4], cc[5], cc[6], cc[7],
                         af[kk][0], af[kk][1], af[kk][2], af[kk][3], bf[kk][1], bf[kk][3]);
            }
            // epilogue: d = sqrt(max(t_row - 2*cross, eps)); accumulate over channels
#pragma unroll
            for (int h = 0; h < 2; h++) {        // n8 sub-tile
#pragma unroll
                for (int e = 0; e < 4; e++) {
                    float trow = (e < 2) ? t0 : t1;
                    float d2 = fmaf(-2.f, cc[h * 4 + e], trow);
                    ds[t * 8 + h * 4 + e] += fast_sqrt(fmaxf(d2, 1e-12f));
                }
            }
        }
    }

    // ---- min over windows ----
    if (tid < K_) s_min[tid] = 0x7F800000;
    __syncthreads();

    const bool v0 = (wbase + rl0) < W_;
    const bool v1 = (wbase + rl1) < W_;
#pragma unroll
    for (int t = 0; t < 8; t++) {
#pragma unroll
        for (int h = 0; h < 2; h++) {
#pragma unroll
            for (int j = 0; j < 2; j++) {   // the two cols 2q, 2q+1
                float a0 = v0 ? ds[t * 8 + h * 4 + j]     : CUDART_INF_F;
                float a1 = v1 ? ds[t * 8 + h * 4 + 2 + j] : CUDART_INF_F;
                float m = fminf(a0, a1);
#pragma unroll
                for (int o = 4; o < 32; o <<= 1) m = fminf(m, __shfl_xor_sync(0xffffffffu, m, o));
                if (g == 0) {
                    int col = t * 16 + h * 8 + q * 2 + j;
                    atomicMin(&s_min[col], __float_as_int(m));
                }
            }
        }
    }
    __syncthreads();
    if (tid < K_) atomicMin((int*)&out[(size_t)n * K_ + tid], s_min[tid]);
}

// ---------------- launch ----------------
extern "C" void kernel_launch(void* const* d_in, const int* in_sizes, int n_in,
                              void* d_out, int out_size) {
    const float* x  = (const float*)d_in[0];   // (64, 8, 2048)
    const float* sh = (const float*)d_in[1];   // (8, 128, 64)
    float* out = (float*)d_out;                // (64, 1, 128)

    prep_kernel<<<dim3(C_, 4), 1024>>>(sh, out);
    min_dist_kernel<<<dim3(NWT, N_), 256>>>(x, out);
}

// round 4
// speedup vs baseline: 2.9832x; 1.2169x over previous
#include <cuda_runtime.h>
#include <cuda_bf16.h>
#include <cstdint>
#include <math_constants.h>

#define N_  64
#define C_  8
#define L_  2048
#define S_  64
#define K_  128
#define W_  (L_ - S_ + 1)          /* 1985 */
#define WT  128
#define NWT ((W_ + WT - 1) / WT)   /* 16 */
#define PAD 72                     /* row pitch in bf16 (144B): conflict-free ldmatrix */

// ---- dynamic smem layout (bytes) ----
#define SM_A      0                /* 2 x 18432 */
#define SM_B      36864            /* 2 x 18432 */
#define SM_STRIP  73728            /* 2 x 192 f32 */
#define SM_SQX    75264            /* 2 x 128 f32 */
#define SM_MIN    76288            /* 128 int */
#define SM_TOTAL  76800

// ---------------- device scratch ----------------
__device__ __align__(16) __nv_bfloat16 g_shb[C_][K_ * PAD]; // z-normed shapelets, padded rows

// ---------------- helpers ----------------
__device__ __forceinline__ uint32_t smem_u32(const void* p) {
    uint32_t a;
    asm("{ .reg .u64 t; cvta.to.shared.u64 t, %1; cvt.u32.u64 %0, t; }" : "=r"(a) : "l"(p));
    return a;
}
__device__ __forceinline__ float fast_sqrt(float x) {
    float r; asm("sqrt.approx.f32 %0, %1;" : "=f"(r) : "f"(x)); return r;
}
__device__ __forceinline__ void ldmatrix_x4(uint32_t& r0, uint32_t& r1, uint32_t& r2, uint32_t& r3,
                                            uint32_t addr) {
    asm volatile("ldmatrix.sync.aligned.m8n8.x4.shared.b16 {%0,%1,%2,%3}, [%4];"
                 : "=r"(r0), "=r"(r1), "=r"(r2), "=r"(r3) : "r"(addr));
}
__device__ __forceinline__ void mma_bf16(float& c0, float& c1, float& c2, float& c3,
                                         uint32_t a0, uint32_t a1, uint32_t a2, uint32_t a3,
                                         uint32_t b0, uint32_t b1) {
    asm volatile("mma.sync.aligned.m16n8k16.row.col.f32.bf16.bf16.f32 "
                 "{%0,%1,%2,%3}, {%4,%5,%6,%7}, {%8,%9}, {%0,%1,%2,%3};"
                 : "+f"(c0), "+f"(c1), "+f"(c2), "+f"(c3)
                 : "r"(a0), "r"(a1), "r"(a2), "r"(a3), "r"(b0), "r"(b1));
}

// ---------------- prep: z-norm shapelets -> padded bf16; init out ----------------
__global__ void prep_kernel(const float* __restrict__ sh, float* __restrict__ out) {
    int c = blockIdx.x;
    int wid = threadIdx.x >> 5, lane = threadIdx.x & 31;
    int k = blockIdx.y * 32 + wid;
    const float* p = sh + ((size_t)c * K_ + k) * S_;

    float a = p[lane], b = p[lane + 32];
    float s = a + b;
#pragma unroll
    for (int o = 16; o > 0; o >>= 1) s += __shfl_xor_sync(0xffffffffu, s, o);
    float mu = s * (1.0f / S_);
    float da = a - mu, db = b - mu;
    float v = da * da + db * db;
#pragma unroll
    for (int o = 16; o > 0; o >>= 1) v += __shfl_xor_sync(0xffffffffu, v, o);
    float inv = rsqrtf(v * (1.0f / S_));

    __nv_bfloat16* row = &g_shb[c][(size_t)k * PAD];
    row[lane]      = __float2bfloat16_rn(da * inv);
    row[lane + 32] = __float2bfloat16_rn(db * inv);

    if (c == 0) {
        int i = blockIdx.y * 1024 + threadIdx.x;
        out[i] = CUDART_INF_F;
        out[i + 4096] = CUDART_INF_F;
    }
}

// ---------------- main kernel ----------------
// 512 threads (16 warps). Warp w: row-group (w&7)*16, k-half (w>>3)*64.
__global__ void __launch_bounds__(512, 1)
min_dist_kernel(const float* __restrict__ x, float* __restrict__ out) {
    extern __shared__ __align__(16) char smem[];
    const int tid = threadIdx.x, w = tid >> 5, lane = tid & 31;
    const int kh = w >> 3, wr = w & 7;
    const int g = lane >> 2, q = lane & 3;
    const int rl0 = wr * 16 + g, rl1 = rl0 + 8;
    const int n = blockIdx.y, wbase = blockIdx.x * WT;
    const float* xrow_base = x + (size_t)n * C_ * L_;

    int* s_min = (int*)(smem + SM_MIN);

    float ds[32];
#pragma unroll
    for (int i = 0; i < 32; i++) ds[i] = 0.f;

    float4 breg[3];
    float  sreg = 0.f;

    // ---- staging helpers ----
    auto stage_ldg = [&](int c) {
        const float4* bsrc = (const float4*)&g_shb[c][0];
#pragma unroll
        for (int i = 0; i < 3; i++) {
            int idx = tid + i * 512;
            if (idx < (K_ * PAD * 2) / 16) breg[i] = bsrc[idx];
        }
        if (tid < WT + S_) {
            int gi = wbase + tid;
            sreg = (gi < L_) ? xrow_base[(size_t)c * L_ + gi] : 0.f;
        }
    };
    auto stage_sts = [&](int buf) {
        float4* bdst = (float4*)(smem + SM_B + buf * 18432);
#pragma unroll
        for (int i = 0; i < 3; i++) {
            int idx = tid + i * 512;
            if (idx < (K_ * PAD * 2) / 16) bdst[idx] = breg[i];
        }
        if (tid < WT + S_) ((float*)(smem + SM_STRIP + buf * 768))[tid] = sreg;
    };
    auto build = [&](int buf) {  // after sync: Toeplitz A + sqx
        const float* strip = (const float*)(smem + SM_STRIP + buf * 768);
        int row = tid >> 2, p = (tid & 3) * 16;
        const float* src = &strip[row];
        __nv_bfloat162* arow = (__nv_bfloat162*)((__nv_bfloat16*)(smem + SM_A + buf * 18432)
                                                 + (size_t)row * PAD + p);
#pragma unroll
        for (int j = 0; j < 8; j++)
            arow[j] = __floats2bfloat162_rn(src[p + 2 * j], src[p + 2 * j + 1]);
        float a = 0.f;
#pragma unroll
        for (int i = 0; i < 16; i++) { float vv = src[p + i]; a = fmaf(vv, vv, a); }
        a += __shfl_xor_sync(0xffffffffu, a, 1);
        a += __shfl_xor_sync(0xffffffffu, a, 2);
        if ((tid & 3) == 0) ((float*)(smem + SM_SQX + buf * 512))[row] = a;
    };
    auto compute = [&](int buf) {
        const float* sqx = (const float*)(smem + SM_SQX + buf * 512);
        uint32_t abase = smem_u32(smem + SM_A + buf * 18432)
                       + (uint32_t)(wr * 16 + (lane & 15)) * (PAD * 2) + (lane >> 4) * 16;
        uint32_t bbase = smem_u32(smem + SM_B + buf * 18432)
                       + (uint32_t)(kh * 64 + (lane & 15)) * (PAD * 2) + (lane >> 4) * 16;
        uint32_t af[4][4];
#pragma unroll
        for (int kk = 0; kk < 4; kk++)
            ldmatrix_x4(af[kk][0], af[kk][1], af[kk][2], af[kk][3], abase + kk * 32);
        const float t0 = sqx[rl0] + (float)S_;   // sqs(z-norm) == S exactly
        const float t1 = sqx[rl1] + (float)S_;
#pragma unroll
        for (int t = 0; t < 4; t++) {
            uint32_t bf[4][4];
            uint32_t ba = bbase + (uint32_t)t * (16 * PAD * 2);
#pragma unroll
            for (int kk = 0; kk < 4; kk++)
                ldmatrix_x4(bf[kk][0], bf[kk][1], bf[kk][2], bf[kk][3], ba + kk * 32);
            float cc[8];
#pragma unroll
            for (int e = 0; e < 8; e++) cc[e] = 0.f;
#pragma unroll
            for (int kk = 0; kk < 4; kk++) {
                mma_bf16(cc[0], cc[1], cc[2], cc[3],
                         af[kk][0], af[kk][1], af[kk][2], af[kk][3], bf[kk][0], bf[kk][2]);
                mma_bf16(cc[4], cc[5], cc[6], cc[7],
                         af[kk][0], af[kk][1], af[kk][2], af[kk][3], bf[kk][1], bf[kk][3]);
            }
#pragma unroll
            for (int h = 0; h < 2; h++)
#pragma unroll
                for (int e = 0; e < 4; e++) {
                    float trow = (e < 2) ? t0 : t1;
                    float d2 = fmaf(-2.f, cc[h * 4 + e], trow);
                    ds[t * 8 + h * 4 + e] += fast_sqrt(fmaxf(d2, 1e-12f));
                }
        }
    };

    // ---- prologue ----
    stage_ldg(0);
    stage_sts(0);
    __syncthreads();
    build(0);
    __syncthreads();

    // ---- pipelined channel loop ----
    for (int c = 0; c < C_; c++) {
        const int buf = c & 1;
        if (c + 1 < C_) stage_ldg(c + 1);   // LDGs fly under compute
        compute(buf);
        if (c + 1 < C_) {
            stage_sts(buf ^ 1);
            __syncthreads();
            build(buf ^ 1);
        }
        __syncthreads();
    }

    // ---- min over windows ----
    if (tid < K_) s_min[tid] = 0x7F800000;
    __syncthreads();
    const bool v0 = (wbase + rl0) < W_;
    const bool v1 = (wbase + rl1) < W_;
#pragma unroll
    for (int t = 0; t < 4; t++)
#pragma unroll
        for (int h = 0; h < 2; h++)
#pragma unroll
            for (int j = 0; j < 2; j++) {
                float a0 = v0 ? ds[t * 8 + h * 4 + j]     : CUDART_INF_F;
                float a1 = v1 ? ds[t * 8 + h * 4 + 2 + j] : CUDART_INF_F;
                float m = fminf(a0, a1);
#pragma unroll
                for (int o = 4; o < 32; o <<= 1) m = fminf(m, __shfl_xor_sync(0xffffffffu, m, o));
                if (g == 0) {
                    int col = kh * 64 + t * 16 + h * 8 + q * 2 + j;
                    atomicMin(&s_min[col], __float_as_int(m));
                }
            }
    __syncthreads();
    if (tid < K_) atomicMin((int*)&out[(size_t)n * K_ + tid], s_min[tid]);
}

// ---------------- launch ----------------
extern "C" void kernel_launch(void* const* d_in, const int* in_sizes, int n_in,
                              void* d_out, int out_size) {
    const float* x  = (const float*)d_in[0];   // (64, 8, 2048)
    const float* sh = (const float*)d_in[1];   // (8, 128, 64)
    float* out = (float*)d_out;                // (64, 1, 128)

    cudaFuncSetAttribute(min_dist_kernel, cudaFuncAttributeMaxDynamicSharedMemorySize, SM_TOTAL);

    prep_kernel<<<dim3(C_, 4), 1024>>>(sh, out);
    min_dist_kernel<<<dim3(NWT, N_), 512, SM_TOTAL>>>(x, out);
}